// round 9
// baseline (speedup 1.0000x reference)
#include <cuda_runtime.h>
#include <cstdint>
#include <math.h>

#define DEV_INLINE __device__ __forceinline__

// Fixed problem dims
#define MAX_B 2048
#define MAX_N 16384
#define MAX_C 2048
#define NTMAX 128

// ---- device-global scratch (referenced ONLY from device code!) ----
__device__ __align__(16) int8_t g_qA[(size_t)MAX_B * MAX_C];   // 4 MB
__device__ __align__(16) int8_t g_qB[(size_t)MAX_N * MAX_C];   // 33.5 MB
__device__ __align__(16) float g_sA[MAX_B];
__device__ __align__(16) float g_sB[MAX_N];
__device__ __align__(16) float g_pos_part[(size_t)MAX_B * NTMAX];
__device__ __align__(16) float g_neg_part[(size_t)MAX_B * NTMAX];
__device__ __align__(16) float g_loss[MAX_B];

// ---------------- helpers ----------------
DEV_INLINE uint32_t smem_u32(const void* p) {
    uint32_t a;
    asm("{ .reg .u64 t; cvta.to.shared.u64 t, %1; cvt.u32.u64 %0, t; }"
        : "=r"(a) : "l"(p));
    return a;
}

DEV_INLINE uint32_t swz(uint32_t off) {            // SW128-style xor swizzle
    return off ^ ((off >> 3) & 0x70);
}

DEV_INLINE void cp16(uint32_t s, const void* g) {
    asm volatile("cp.async.cg.shared.global [%0], [%1], 16;\n"
                 :: "r"(s), "l"(g));
}
#define CP_COMMIT() asm volatile("cp.async.commit_group;\n" ::: "memory")
#define CP_WAIT2()  asm volatile("cp.async.wait_group 2;\n" ::: "memory")

#define LDSM4(R, addr)                                                        \
    asm volatile("ldmatrix.sync.aligned.m8n8.x4.shared.b16 {%0,%1,%2,%3},[%4];" \
                 : "=r"((R)[0]), "=r"((R)[1]), "=r"((R)[2]), "=r"((R)[3])     \
                 : "r"(addr))

#define IMMA16832(d, a, b0, b1)                                               \
    asm volatile(                                                             \
        "mma.sync.aligned.m16n8k32.row.col.s32.s8.s8.s32 "                    \
        "{%0,%1,%2,%3},{%4,%5,%6,%7},{%8,%9},{%0,%1,%2,%3};"                  \
        : "+r"((d)[0]), "+r"((d)[1]), "+r"((d)[2]), "+r"((d)[3])              \
        : "r"((a)[0]), "r"((a)[1]), "r"((a)[2]), "r"((a)[3]),                 \
          "r"(b0), "r"(b1))

// ---------------- kernels ----------------

// per-row symmetric int8 quantization; dst/scales resolved IN DEVICE CODE.
__global__ __launch_bounds__(256)
void k_quant(const float* __restrict__ src, int which, int C) {
    int8_t* dst   = which ? g_qB : g_qA;
    float* scales = which ? g_sB : g_sA;
    int row = blockIdx.x, tid = threadIdx.x;
    const float4* s4 = (const float4*)(src + (size_t)row * C);
    float4 v0 = s4[tid];
    float4 v1 = s4[tid + 256];
    float m = fmaxf(fmaxf(fmaxf(fabsf(v0.x), fabsf(v0.y)),
                          fmaxf(fabsf(v0.z), fabsf(v0.w))),
                    fmaxf(fmaxf(fabsf(v1.x), fabsf(v1.y)),
                          fmaxf(fabsf(v1.z), fabsf(v1.w))));
#pragma unroll
    for (int o = 16; o > 0; o >>= 1)
        m = fmaxf(m, __shfl_xor_sync(0xFFFFFFFFu, m, o));
    __shared__ float wmax[8];
    if ((tid & 31) == 0) wmax[tid >> 5] = m;
    __syncthreads();
    float mv = wmax[0];
#pragma unroll
    for (int w = 1; w < 8; w++) mv = fmaxf(mv, wmax[w]);

    float inv = (mv > 0.0f) ? 127.0f / mv : 0.0f;
    if (tid == 0) scales[row] = mv * (1.0f / 127.0f);
    char4 q0, q1;
    q0.x = (char)__float2int_rn(v0.x * inv);
    q0.y = (char)__float2int_rn(v0.y * inv);
    q0.z = (char)__float2int_rn(v0.z * inv);
    q0.w = (char)__float2int_rn(v0.w * inv);
    q1.x = (char)__float2int_rn(v1.x * inv);
    q1.y = (char)__float2int_rn(v1.y * inv);
    q1.z = (char)__float2int_rn(v1.z * inv);
    q1.w = (char)__float2int_rn(v1.w * inv);
    *(char4*)(dst + (size_t)row * C + 4 * tid) = q0;
    *(char4*)(dst + (size_t)row * C + 1024 + 4 * tid) = q1;
}

// GEMM tile config: int8, BK = 128 bytes = one SW128 row
#define BM 128
#define BN 256
#define BKB 128
#define STAGES 3
#define A_BYTES (BM * BKB)                  // 16384
#define B_BYTES (BN * BKB)                  // 32768
#define STAGE_BYTES (A_BYTES + B_BYTES)     // 49152
#define SM_SLAB (STAGES * STAGE_BYTES)      // 147456 : labels [256]
#define SM_SCAL (SM_SLAB + 1024)            // col scales [256]
#define SM_REDP (SM_SCAL + 1024)            // [8][128] floats
#define SM_REDN (SM_REDP + 4096)
#define SMEM_SZ (SM_REDN + 4096)            // 157696

DEV_INLINE void load_stage(uint32_t sb, int stage, int kc,
                           const int8_t* pa, const int8_t* pb,
                           int tid, int C) {
    uint32_t sA = sb + stage * STAGE_BYTES;
    uint32_t sB = sA + A_BYTES;
    const int8_t* a0 = pa + (size_t)kc * BKB;
    const int8_t* b0 = pb + (size_t)kc * BKB;
#pragma unroll
    for (int j = 0; j < 2; j++) {                   // A: 1024 16B-chunks
        int id = tid + j * 512;
        int r = id >> 3, c = id & 7;
        uint32_t off = swz((uint32_t)(r * 128 + c * 16));
        cp16(sA + off, a0 + (size_t)r * C + c * 16);
    }
#pragma unroll
    for (int j = 0; j < 4; j++) {                   // B: 2048 16B-chunks
        int id = tid + j * 512;
        int r = id >> 3, c = id & 7;
        uint32_t off = swz((uint32_t)(r * 128 + c * 16));
        cp16(sB + off, b0 + (size_t)r * C + c * 16);
    }
}

// int8 GEMM + fused exp/mask/min/sum epilogue.
// grid = (B/128, N/256); blockIdx.x fastest -> B col-tile reused in L2.
__global__ __launch_bounds__(512, 1)
void k_gemm(const int* __restrict__ labels, const int* __restrict__ labels_s,
            int Bq, int N, int C) {
    extern __shared__ unsigned char smem[];
    uint32_t sb = smem_u32(smem);
    int tid = threadIdx.x;
    int lane = tid & 31, wid = tid >> 5;
    int warp_m = wid >> 3, warp_n = wid & 7;       // 2 x 8 warp grid
    int row0 = blockIdx.x * BM;
    int col0 = blockIdx.y * BN;

    int* slab = (int*)(smem + SM_SLAB);
    float* sscale = (float*)(smem + SM_SCAL);
    if (tid < 256) {
        slab[tid] = labels_s[col0 + tid];
        sscale[tid] = g_sB[col0 + tid];
    }

    const int8_t* pa = g_qA + (size_t)row0 * C;
    const int8_t* pb = g_qB + (size_t)col0 * C;

    int acc[4][4][4];
#pragma unroll
    for (int i = 0; i < 4; i++)
#pragma unroll
        for (int j = 0; j < 4; j++)
#pragma unroll
            for (int k = 0; k < 4; k++) acc[i][j][k] = 0;

    int KC = C / BKB;                               // 16
    load_stage(sb, 0, 0, pa, pb, tid, C); CP_COMMIT();
    load_stage(sb, 1, 1, pa, pb, tid, C); CP_COMMIT();

    int lrow = lane & 15;
    int lcolb = (lane >> 4) << 4;                   // byte col offset 0/16
    uint32_t kxor = (uint32_t)((lrow & 7) << 4);    // swizzle xor (row&7 == lrow&7)
    uint32_t arow[4], brow[2];
#pragma unroll
    for (int mi = 0; mi < 4; mi++)
        arow[mi] = (uint32_t)((warp_m * 64 + mi * 16 + lrow) * 128);
#pragma unroll
    for (int g = 0; g < 2; g++)
        brow[g] = (uint32_t)((warp_n * 32 + g * 16 + lrow) * 128);

    for (int kc = 0; kc < KC; kc++) {
        __syncthreads();                            // stage (kc+2)%3 free to overwrite
        if (kc + 2 < KC) load_stage(sb, (kc + 2) % STAGES, kc + 2, pa, pb, tid, C);
        CP_COMMIT();
        CP_WAIT2();                                 // stage kc data arrived (this thread)
        __syncthreads();                            // ... and all threads'

        uint32_t stA = sb + (kc % STAGES) * STAGE_BYTES;
        uint32_t stB = stA + A_BYTES;
#pragma unroll
        for (int ks = 0; ks < 4; ks++) {            // 4 x k32 covers 128 bytes
            uint32_t kb = ((uint32_t)(ks * 32) + lcolb) ^ kxor;
            uint32_t a[4][4], b[2][4];
#pragma unroll
            for (int mi = 0; mi < 4; mi++) LDSM4(a[mi], stA + arow[mi] + kb);
#pragma unroll
            for (int g = 0; g < 2; g++)    LDSM4(b[g], stB + brow[g] + kb);
#pragma unroll
            for (int mi = 0; mi < 4; mi++) {
#pragma unroll
                for (int nj = 0; nj < 4; nj++) {
                    int g = nj >> 1;
                    if (nj & 1) { IMMA16832(acc[mi][nj], a[mi], b[g][1], b[g][3]); }
                    else        { IMMA16832(acc[mi][nj], a[mi], b[g][0], b[g][2]); }
                }
            }
        }
    }

    // ---- fused epilogue: sim = acc * sA[row] * sB[col]; e = exp(sim*20) ----
    int rbase = warp_m * 64 + (lane >> 2);
    int labr[8]; float fr[8];
#pragma unroll
    for (int mi = 0; mi < 4; mi++) {
        int r0 = row0 + rbase + mi * 16;
        labr[mi * 2]     = labels[r0];
        labr[mi * 2 + 1] = labels[r0 + 8];
        fr[mi * 2]       = g_sA[r0] * 20.0f;
        fr[mi * 2 + 1]   = g_sA[r0 + 8] * 20.0f;
    }
    int labc[8]; float fc[8];
#pragma unroll
    for (int ni = 0; ni < 4; ni++) {
        int c0 = warp_n * 32 + ni * 8 + 2 * (lane & 3);
        labc[ni * 2]     = slab[c0];
        labc[ni * 2 + 1] = slab[c0 + 1];
        fc[ni * 2]       = sscale[c0];
        fc[ni * 2 + 1]   = sscale[c0 + 1];
    }
    float pm[8], ns[8];
#pragma unroll
    for (int i = 0; i < 8; i++) { pm[i] = INFINITY; ns[i] = 0.0f; }

#pragma unroll
    for (int mi = 0; mi < 4; mi++) {
#pragma unroll
        for (int ni = 0; ni < 4; ni++) {
            float e0 = __expf((float)acc[mi][ni][0] * (fr[mi * 2]     * fc[ni * 2]));
            float e1 = __expf((float)acc[mi][ni][1] * (fr[mi * 2]     * fc[ni * 2 + 1]));
            float e2 = __expf((float)acc[mi][ni][2] * (fr[mi * 2 + 1] * fc[ni * 2]));
            float e3 = __expf((float)acc[mi][ni][3] * (fr[mi * 2 + 1] * fc[ni * 2 + 1]));
            int l0 = labc[ni * 2], l1 = labc[ni * 2 + 1];
            int r0 = labr[mi * 2], r1 = labr[mi * 2 + 1];
            if (l0 == r0) pm[mi * 2] = fminf(pm[mi * 2], e0); else ns[mi * 2] += e0;
            if (l1 == r0) pm[mi * 2] = fminf(pm[mi * 2], e1); else ns[mi * 2] += e1;
            if (l0 == r1) pm[mi * 2 + 1] = fminf(pm[mi * 2 + 1], e2); else ns[mi * 2 + 1] += e2;
            if (l1 == r1) pm[mi * 2 + 1] = fminf(pm[mi * 2 + 1], e3); else ns[mi * 2 + 1] += e3;
        }
    }
#pragma unroll
    for (int i = 0; i < 8; i++) {
        pm[i] = fminf(pm[i], __shfl_xor_sync(0xFFFFFFFFu, pm[i], 1));
        pm[i] = fminf(pm[i], __shfl_xor_sync(0xFFFFFFFFu, pm[i], 2));
        ns[i] += __shfl_xor_sync(0xFFFFFFFFu, ns[i], 1);
        ns[i] += __shfl_xor_sync(0xFFFFFFFFu, ns[i], 2);
    }

    float* red_p = (float*)(smem + SM_REDP);   // [8][128]
    float* red_n = (float*)(smem + SM_REDN);
    if ((lane & 3) == 0) {
#pragma unroll
        for (int mi = 0; mi < 4; mi++) {
            int r = warp_m * 64 + mi * 16 + (lane >> 2);
            red_p[warp_n * 128 + r] = pm[mi * 2];
            red_n[warp_n * 128 + r] = ns[mi * 2];
            red_p[warp_n * 128 + r + 8] = pm[mi * 2 + 1];
            red_n[warp_n * 128 + r + 8] = ns[mi * 2 + 1];
        }
    }
    __syncthreads();
    if (tid < 128) {
        float p = INFINITY, n = 0.0f;
#pragma unroll
        for (int w = 0; w < 8; w++) {
            p = fminf(p, red_p[w * 128 + tid]);
            n += red_n[w * 128 + tid];
        }
        int nt = N / BN;
        g_pos_part[(size_t)(row0 + tid) * nt + blockIdx.y] = p;
        g_neg_part[(size_t)(row0 + tid) * nt + blockIdx.y] = n;
    }
}

// per-row reduce of col-tile partials -> loss[row]  (deterministic tree)
__global__ void k_row(int nt) {
    int row = blockIdx.x, t = threadIdx.x;
    __shared__ float spm[128], sns[128];
    float pmv = INFINITY, nsv = 0.0f;
    if (t < nt) {
        pmv = g_pos_part[(size_t)row * nt + t];
        nsv = g_neg_part[(size_t)row * nt + t];
    }
    spm[t] = pmv; sns[t] = nsv;
    __syncthreads();
    for (int st = 64; st > 0; st >>= 1) {
        if (t < st) {
            spm[t] = fminf(spm[t], spm[t + st]);
            sns[t] += sns[t + st];
        }
        __syncthreads();
    }
    if (t == 0) {
        float p = spm[0], n = sns[0];
        g_loss[row] = -logf(p / (p + n + 1e-6f) + 1e-6f);
    }
}

// mean over rows -> scalar output
__global__ void k_mean(float* __restrict__ out, int Bq) {
    __shared__ float s[1024];
    float accv = 0.0f;
    for (int i = threadIdx.x; i < Bq; i += 1024) accv += g_loss[i];
    s[threadIdx.x] = accv;
    __syncthreads();
    for (int st = 512; st > 0; st >>= 1) {
        if (threadIdx.x < st) s[threadIdx.x] += s[threadIdx.x + st];
        __syncthreads();
    }
    if (threadIdx.x == 0) out[0] = s[0] / (float)Bq;
}

extern "C" void kernel_launch(void* const* d_in, const int* in_sizes, int n_in,
                              void* d_out, int out_size) {
    const float* feats    = (const float*)d_in[0];
    const float* feats_s  = (const float*)d_in[1];
    const int*   labels   = (const int*)d_in[2];
    const int*   labels_s = (const int*)d_in[3];

    int Bq = in_sizes[2];            // 2048
    int N  = in_sizes[3];            // 16384
    int C  = in_sizes[0] / Bq;       // 2048

    k_quant<<<Bq, 256>>>(feats,   0, C);
    k_quant<<<N,  256>>>(feats_s, 1, C);

    cudaFuncSetAttribute(k_gemm, cudaFuncAttributeMaxDynamicSharedMemorySize, SMEM_SZ);
    dim3 grid(Bq / BM, N / BN);
    k_gemm<<<grid, 512, SMEM_SZ>>>(labels, labels_s, Bq, N, C);

    k_row<<<Bq, 128>>>(N / BN);
    k_mean<<<1, 1024>>>((float*)d_out, Bq);
}

// round 12
// speedup vs baseline: 2.4110x; 2.4110x over previous
#include <cuda_runtime.h>
#include <cuda_fp16.h>
#include <cstdint>
#include <math.h>

#define DEV_INLINE __device__ __forceinline__

// Fixed problem dims
#define MAX_B 2048
#define MAX_N 16384
#define MAX_C 2048
#define NTMAX 128

// ---- device-global scratch (referenced only from device code) ----
__device__ __align__(16) __half g_feats[MAX_B * MAX_C];        // 8.4 MB
__device__ __align__(16) __half g_fs[(size_t)MAX_N * MAX_C];   // 67 MB
__device__ __align__(16) float g_pos_part[(size_t)MAX_B * NTMAX];
__device__ __align__(16) float g_neg_part[(size_t)MAX_B * NTMAX];
__device__ __align__(16) float g_loss[MAX_B];

// ---------------- helpers ----------------
DEV_INLINE uint32_t smem_u32(const void* p) {
    uint32_t a;
    asm("{ .reg .u64 t; cvta.to.shared.u64 t, %1; cvt.u32.u64 %0, t; }"
        : "=r"(a) : "l"(p));
    return a;
}

DEV_INLINE uint32_t swz(uint32_t off) {            // SW128-style xor swizzle
    return off ^ ((off >> 3) & 0x70);
}

DEV_INLINE void cp16(uint32_t s, const void* g) {
    asm volatile("cp.async.cg.shared.global [%0], [%1], 16;\n"
                 :: "r"(s), "l"(g));
}
#define CP_COMMIT() asm volatile("cp.async.commit_group;\n" ::: "memory")
#define CP_WAIT2()  asm volatile("cp.async.wait_group 2;\n" ::: "memory")

#define LDSM4(R, addr)                                                        \
    asm volatile("ldmatrix.sync.aligned.m8n8.x4.shared.b16 {%0,%1,%2,%3},[%4];" \
                 : "=r"((R)[0]), "=r"((R)[1]), "=r"((R)[2]), "=r"((R)[3])     \
                 : "r"(addr))

// fp16 x fp16 -> fp16 accumulators (2 regs = 4 half)
#define MMAF16(d, a, b0, b1)                                                  \
    asm volatile(                                                             \
        "mma.sync.aligned.m16n8k16.row.col.f16.f16.f16.f16 "                  \
        "{%0,%1},{%2,%3,%4,%5},{%6,%7},{%0,%1};"                              \
        : "+r"((d)[0]), "+r"((d)[1])                                          \
        : "r"((a)[0]), "r"((a)[1]), "r"((a)[2]), "r"((a)[3]),                 \
          "r"(b0), "r"(b1))

// ---------------- kernels ----------------

// fp32 -> fp16 conversion into device-global scratch
__global__ void k_cvt(const float* __restrict__ src, long n4, int which) {
    __half* dst = which ? g_fs : g_feats;
    long i = (long)blockIdx.x * blockDim.x + threadIdx.x;
    long stride = (long)gridDim.x * blockDim.x;
    const float4* s4 = (const float4*)src;
    __half2* d2 = (__half2*)dst;
    for (long j = i; j < n4; j += stride) {
        float4 v = s4[j];
        d2[2 * j]     = __floats2half2_rn(v.x, v.y);
        d2[2 * j + 1] = __floats2half2_rn(v.z, v.w);
    }
}

// GEMM tile config: 8 warps, each owning a 64x64 output tile
#define BM 128
#define BN 256
#define BK 64
#define STAGES 3
#define A_BYTES (BM * BK * 2)               // 16384
#define B_BYTES (BN * BK * 2)               // 32768
#define STAGE_BYTES (A_BYTES + B_BYTES)     // 49152
#define SM_SLAB (STAGES * STAGE_BYTES)      // 147456 : labels [256]
#define SM_REDP (SM_SLAB + 1024)            // [4][128] floats
#define SM_REDN (SM_REDP + 2048)
#define SMEM_SZ (SM_REDN + 2048)            // 152576

DEV_INLINE void load_stage(uint32_t sb, int stage, int kc,
                           const __half* pa, const __half* pb,
                           int tid, int C) {
    uint32_t sA = sb + stage * STAGE_BYTES;
    uint32_t sB = sA + A_BYTES;
    const __half* a0 = pa + (size_t)kc * BK;
    const __half* b0 = pb + (size_t)kc * BK;
#pragma unroll
    for (int j = 0; j < 4; j++) {                   // A: 1024 16B-chunks / 256 thr
        int id = tid + j * 256;
        int r = id >> 3, c = id & 7;
        uint32_t off = swz((uint32_t)(r * 128 + c * 16));
        cp16(sA + off, a0 + (size_t)r * C + c * 8);
    }
#pragma unroll
    for (int j = 0; j < 8; j++) {                   // B: 2048 16B-chunks / 256 thr
        int id = tid + j * 256;
        int r = id >> 3, c = id & 7;
        uint32_t off = swz((uint32_t)(r * 128 + c * 16));
        cp16(sB + off, b0 + (size_t)r * C + c * 8);
    }
}

// GEMM + fused exp/mask/min/sum epilogue.
// grid = (B/128, N/256); blockIdx.x fastest -> B col-tile reused in L2.
__global__ __launch_bounds__(256, 1)
void k_gemm(const int* __restrict__ labels, const int* __restrict__ labels_s,
            int Bq, int N, int C) {
    extern __shared__ unsigned char smem[];
    uint32_t sb = smem_u32(smem);
    int tid = threadIdx.x;
    int lane = tid & 31, wid = tid >> 5;
    int warp_m = wid >> 2, warp_n = wid & 3;       // 2 x 4 warps of 64x64
    int row0 = blockIdx.x * BM;
    int col0 = blockIdx.y * BN;

    int* slab = (int*)(smem + SM_SLAB);
    slab[tid] = labels_s[col0 + tid];              // 256 labels, 256 threads

    const __half* pa = g_feats + (size_t)row0 * C;
    const __half* pb = g_fs + (size_t)col0 * C;

    uint32_t acc[4][8][2];                          // f16x2 accumulators, 64 regs
#pragma unroll
    for (int i = 0; i < 4; i++)
#pragma unroll
        for (int j = 0; j < 8; j++) { acc[i][j][0] = 0u; acc[i][j][1] = 0u; }

    int KC = C / BK;                                // 32
    load_stage(sb, 0, 0, pa, pb, tid, C); CP_COMMIT();
    load_stage(sb, 1, 1, pa, pb, tid, C); CP_COMMIT();

    int lrow = lane & 15;
    int lcolb = (lane >> 4) << 4;                   // byte col offset 0/16
    uint32_t kxor = (uint32_t)((lrow & 7) << 4);    // swizzle xor (row&7 == lrow&7)
    uint32_t arow[4], brow[4];
#pragma unroll
    for (int mi = 0; mi < 4; mi++)
        arow[mi] = (uint32_t)((warp_m * 64 + mi * 16 + lrow) * 128);
#pragma unroll
    for (int g = 0; g < 4; g++)
        brow[g] = (uint32_t)((warp_n * 64 + g * 16 + lrow) * 128);

    uint32_t a[2][4][4], b[2][4][4];                // double-buffered fragments

    for (int kc = 0; kc < KC; kc++) {
        __syncthreads();                            // stage (kc+2)%3 free to overwrite
        if (kc + 2 < KC) load_stage(sb, (kc + 2) % STAGES, kc + 2, pa, pb, tid, C);
        CP_COMMIT();
        CP_WAIT2();                                 // stage kc data arrived (this thread)
        __syncthreads();                            // ... and all threads'

        uint32_t stA = sb + (kc % STAGES) * STAGE_BYTES;
        uint32_t stB = stA + A_BYTES;

        {   // prime ks=0 into buffer 0
            uint32_t kb = lcolb ^ kxor;
#pragma unroll
            for (int mi = 0; mi < 4; mi++) LDSM4(a[0][mi], stA + arow[mi] + kb);
#pragma unroll
            for (int g = 0; g < 4; g++)    LDSM4(b[0][g], stB + brow[g] + kb);
        }
#pragma unroll
        for (int ks = 0; ks < 4; ks++) {
            int cur = ks & 1, nxt = cur ^ 1;
            if (ks < 3) {                           // prefetch ks+1 fragments
                uint32_t kb = ((uint32_t)((ks + 1) * 32) + lcolb) ^ kxor;
#pragma unroll
                for (int mi = 0; mi < 4; mi++) LDSM4(a[nxt][mi], stA + arow[mi] + kb);
#pragma unroll
                for (int g = 0; g < 4; g++)    LDSM4(b[nxt][g], stB + brow[g] + kb);
            }
#pragma unroll
            for (int mi = 0; mi < 4; mi++) {
#pragma unroll
                for (int nj = 0; nj < 8; nj++) {
                    int g = nj >> 1;
                    if (nj & 1) { MMAF16(acc[mi][nj], a[cur][mi], b[cur][g][1], b[cur][g][3]); }
                    else        { MMAF16(acc[mi][nj], a[cur][mi], b[cur][g][0], b[cur][g][2]); }
                }
            }
        }
    }

    // ---- fused epilogue ----
    // f16-acc layout: reg0 = {row r, cols c0,c0+1}, reg1 = {row r+8, cols c0,c0+1}
    int rbase = warp_m * 64 + (lane >> 2);
    int labr[8];
#pragma unroll
    for (int mi = 0; mi < 4; mi++) {
        labr[mi * 2]     = labels[row0 + rbase + mi * 16];
        labr[mi * 2 + 1] = labels[row0 + rbase + mi * 16 + 8];
    }
    int labc[16];
#pragma unroll
    for (int nj = 0; nj < 8; nj++) {
        int c0 = warp_n * 64 + nj * 8 + 2 * (lane & 3);
        labc[nj * 2]     = slab[c0];
        labc[nj * 2 + 1] = slab[c0 + 1];
    }
    float pm[8], ns[8];
#pragma unroll
    for (int i = 0; i < 8; i++) { pm[i] = INFINITY; ns[i] = 0.0f; }

#pragma unroll
    for (int mi = 0; mi < 4; mi++) {
#pragma unroll
        for (int nj = 0; nj < 8; nj++) {
            __half2 h01 = *reinterpret_cast<__half2*>(&acc[mi][nj][0]);
            __half2 h23 = *reinterpret_cast<__half2*>(&acc[mi][nj][1]);
            float2 v01 = __half22float2(h01);      // row r   : cols c0, c0+1
            float2 v23 = __half22float2(h23);      // row r+8 : cols c0, c0+1
            float e0 = __expf(v01.x * 20.0f);
            float e1 = __expf(v01.y * 20.0f);
            float e2 = __expf(v23.x * 20.0f);
            float e3 = __expf(v23.y * 20.0f);
            int l0 = labc[nj * 2], l1 = labc[nj * 2 + 1];
            int r0 = labr[mi * 2], r1 = labr[mi * 2 + 1];
            if (l0 == r0) pm[mi * 2] = fminf(pm[mi * 2], e0); else ns[mi * 2] += e0;
            if (l1 == r0) pm[mi * 2] = fminf(pm[mi * 2], e1); else ns[mi * 2] += e1;
            if (l0 == r1) pm[mi * 2 + 1] = fminf(pm[mi * 2 + 1], e2); else ns[mi * 2 + 1] += e2;
            if (l1 == r1) pm[mi * 2 + 1] = fminf(pm[mi * 2 + 1], e3); else ns[mi * 2 + 1] += e3;
        }
    }
#pragma unroll
    for (int i = 0; i < 8; i++) {
        pm[i] = fminf(pm[i], __shfl_xor_sync(0xFFFFFFFFu, pm[i], 1));
        pm[i] = fminf(pm[i], __shfl_xor_sync(0xFFFFFFFFu, pm[i], 2));
        ns[i] += __shfl_xor_sync(0xFFFFFFFFu, ns[i], 1);
        ns[i] += __shfl_xor_sync(0xFFFFFFFFu, ns[i], 2);
    }

    float* red_p = (float*)(smem + SM_REDP);   // [4][128]
    float* red_n = (float*)(smem + SM_REDN);
    if ((lane & 3) == 0) {
#pragma unroll
        for (int mi = 0; mi < 4; mi++) {
            int r = warp_m * 64 + mi * 16 + (lane >> 2);
            red_p[warp_n * 128 + r] = pm[mi * 2];
            red_n[warp_n * 128 + r] = ns[mi * 2];
            red_p[warp_n * 128 + r + 8] = pm[mi * 2 + 1];
            red_n[warp_n * 128 + r + 8] = ns[mi * 2 + 1];
        }
    }
    __syncthreads();
    if (tid < 128) {
        float p = INFINITY, n = 0.0f;
#pragma unroll
        for (int w = 0; w < 4; w++) {
            p = fminf(p, red_p[w * 128 + tid]);
            n += red_n[w * 128 + tid];
        }
        int nt = N / BN;
        g_pos_part[(size_t)(row0 + tid) * nt + blockIdx.y] = p;
        g_neg_part[(size_t)(row0 + tid) * nt + blockIdx.y] = n;
    }
}

// per-row reduce of col-tile partials -> loss[row]  (deterministic tree)
__global__ void k_row(int nt) {
    int row = blockIdx.x, t = threadIdx.x;
    __shared__ float spm[128], sns[128];
    float pmv = INFINITY, nsv = 0.0f;
    if (t < nt) {
        pmv = g_pos_part[(size_t)row * nt + t];
        nsv = g_neg_part[(size_t)row * nt + t];
    }
    spm[t] = pmv; sns[t] = nsv;
    __syncthreads();
    for (int st = 64; st > 0; st >>= 1) {
        if (t < st) {
            spm[t] = fminf(spm[t], spm[t + st]);
            sns[t] += sns[t + st];
        }
        __syncthreads();
    }
    if (t == 0) {
        float p = spm[0], n = sns[0];
        g_loss[row] = -logf(p / (p + n + 1e-6f) + 1e-6f);
    }
}

// mean over rows -> scalar output
__global__ void k_mean(float* __restrict__ out, int Bq) {
    __shared__ float s[1024];
    float accv = 0.0f;
    for (int i = threadIdx.x; i < Bq; i += 1024) accv += g_loss[i];
    s[threadIdx.x] = accv;
    __syncthreads();
    for (int st = 512; st > 0; st >>= 1) {
        if (threadIdx.x < st) s[threadIdx.x] += s[threadIdx.x + st];
        __syncthreads();
    }
    if (threadIdx.x == 0) out[0] = s[0] / (float)Bq;
}

extern "C" void kernel_launch(void* const* d_in, const int* in_sizes, int n_in,
                              void* d_out, int out_size) {
    const float* feats    = (const float*)d_in[0];
    const float* feats_s  = (const float*)d_in[1];
    const int*   labels   = (const int*)d_in[2];
    const int*   labels_s = (const int*)d_in[3];

    int Bq = in_sizes[2];            // 2048
    int N  = in_sizes[3];            // 16384
    int C  = in_sizes[0] / Bq;       // 2048

    long nA4 = ((long)Bq * C) / 4;
    long nB4 = ((long)N * C) / 4;
    k_cvt<<<2048, 256>>>(feats,   nA4, 0);
    k_cvt<<<4096, 256>>>(feats_s, nB4, 1);

    cudaFuncSetAttribute(k_gemm, cudaFuncAttributeMaxDynamicSharedMemorySize, SMEM_SZ);
    dim3 grid(Bq / BM, N / BN);
    k_gemm<<<grid, 256, SMEM_SZ>>>(labels, labels_s, Bq, N, C);

    k_row<<<Bq, 128>>>(N / BN);
    k_mean<<<1, 1024>>>((float*)d_out, Bq);
}